// round 12
// baseline (speedup 1.0000x reference)
#include <cuda_runtime.h>
#include <cuda_bf16.h>

// Problem shape (fixed by the reference)
#define NWALK 4096
#define NIN   24      // NPART*NDIM
#define HID   256
#define TPW   16      // lanes per walker
#define BLOCK 128
#define STR   28      // padded smem stride (words): conflict-free LDS.128 phases

// ---- packed f32x2 helpers (sm_100a FFMA2 path; ptxas never auto-fuses) ----
__device__ __forceinline__ unsigned long long pk2(float lo, float hi) {
    unsigned long long r;
    asm("mov.b64 %0, {%1, %2};" : "=l"(r) : "f"(lo), "f"(hi));
    return r;
}
__device__ __forceinline__ void upk2(unsigned long long v, float& lo, float& hi) {
    asm("mov.b64 {%0, %1}, %2;" : "=f"(lo), "=f"(hi) : "l"(v));
}
__device__ __forceinline__ unsigned long long ffma2(unsigned long long a,
                                                    unsigned long long b,
                                                    unsigned long long c) {
    unsigned long long d;
    asm("fma.rn.f32x2 %0, %1, %2, %3;" : "=l"(d) : "l"(a), "l"(b), "l"(c));
    return d;
}
__device__ __forceinline__ unsigned long long fadd2(unsigned long long a,
                                                    unsigned long long b) {
    unsigned long long d;
    asm("add.rn.f32x2 %0, %1, %2;" : "=l"(d) : "l"(a), "l"(b));
    return d;
}
__device__ __forceinline__ float tanh_hw(float a) {
    float h;
    asm("tanh.approx.f32 %0, %1;" : "=f"(h) : "f"(a));
    return h;
}

__global__ __launch_bounds__(BLOCK, 4)
void kin_kernel(const float* __restrict__ x,
                const float* __restrict__ W1,
                const float* __restrict__ b1,
                const float* __restrict__ W2,
                float* __restrict__ out)
{
    __shared__ float  sW1t[HID * STR];   // [j][i], padded: 28KB
    __shared__ float4 sP[HID];           // (b1_j, W2_j, -2*S_j*W2_j, 0): 4KB

    const int tid = threadIdx.x;

    // ---- Preamble: coalesced high-MLP fill + transpose (one burst) ----
    #pragma unroll
    for (int t = 0; t < (NIN * HID) / BLOCK; t++) {     // 48 coalesced LDGs/thread
        const int k = t * BLOCK + tid;                  // k = i*HID + j
        const int i = k >> 8;
        const int j = k & (HID - 1);
        sW1t[j * STR + i] = W1[k];
    }
    {   // b1, W2 and per-column constants
        const int j0 = tid, j1 = tid + BLOCK;
        const float b0 = b1[j0], b1v = b1[j1];
        const float w0 = W2[j0], w1v = W2[j1];
        __syncthreads();                                // sW1t ready
        float s0 = 0.f, s1 = 0.f;
        #pragma unroll
        for (int i = 0; i < NIN; i++) {
            const float a = sW1t[j0 * STR + i];
            const float b = sW1t[j1 * STR + i];
            s0 = fmaf(a, a, s0);
            s1 = fmaf(b, b, s1);
        }
        sP[j0] = make_float4(b0,  w0,  -2.f * s0 * w0,  0.f);
        sP[j1] = make_float4(b1v, w1v, -2.f * s1 * w1v, 0.f);
    }
    __syncthreads();

    // ---- Main: 1 walker per 16-lane group ----
    const int gt     = blockIdx.x * BLOCK + tid;
    const int walker = gt >> 4;
    const int sub    = gt & (TPW - 1);

    const ulonglong2* z4 = reinterpret_cast<const ulonglong2*>(x + walker * NIN);
    unsigned long long z_pk[12];
    #pragma unroll
    for (int c = 0; c < 6; c++) {
        ulonglong2 v = z4[c];
        z_pk[2*c] = v.x; z_pk[2*c + 1] = v.y;
    }

    unsigned long long g_pk[12];
    #pragma unroll
    for (int q = 0; q < 12; q++) g_pk[q] = 0ull;
    float lap = 0.f;

    #pragma unroll 4
    for (int jj = 0; jj < HID / TPW; jj++) {
        const int j = (jj << 4) + sub;
        const float* wc = &sW1t[j * STR];

        unsigned long long w_pk[12];
        #pragma unroll
        for (int c = 0; c < 6; c++) {
            const float4 v = *reinterpret_cast<const float4*>(wc + 4 * c);  // LDS.128
            w_pk[2*c]     = pk2(v.x, v.y);
            w_pk[2*c + 1] = pk2(v.z, v.w);
        }
        const float4 p = sP[j];                // (b1, W2, -2*S*W2, 0)

        // dot (packed over i): 12 FFMA2, 4 accumulators
        unsigned long long a0 = pk2(p.x, 0.f), a1 = 0ull, a2 = 0ull, a3 = 0ull;
        #pragma unroll
        for (int q = 0; q < 12; q += 4) {
            a0 = ffma2(z_pk[q],     w_pk[q],     a0);
            a1 = ffma2(z_pk[q + 1], w_pk[q + 1], a1);
            a2 = ffma2(z_pk[q + 2], w_pk[q + 2], a2);
            a3 = ffma2(z_pk[q + 3], w_pk[q + 3], a3);
        }
        float lo, hi;
        upk2(fadd2(fadd2(a0, a1), fadd2(a2, a3)), lo, hi);

        // hardware tanh; om = 1-h^2 (non-saturated regime)
        const float h  = tanh_hw(lo + hi);
        const float om = fmaf(-h, h, 1.f);
        const float u  = om * p.y;
        lap = fmaf(om * h, p.z, lap);          // += (1-h^2)*h*(-2*S*W2)

        // gradient accumulation: 12 FFMA2
        const unsigned long long ud = pk2(u, u);
        #pragma unroll
        for (int q = 0; q < 12; q++) g_pk[q] = ffma2(w_pk[q], ud, g_pk[q]);
    }

    // Butterfly reduction across the 16 lanes of this walker
    #pragma unroll
    for (int ofs = 1; ofs < TPW; ofs <<= 1) {
        #pragma unroll
        for (int q = 0; q < 12; q++)
            g_pk[q] = fadd2(g_pk[q], __shfl_xor_sync(0xffffffffu, g_pk[q], ofs));
        lap += __shfl_xor_sync(0xffffffffu, lap, ofs);
    }

    if (sub == 0) {
        unsigned long long gs = 0ull;
        #pragma unroll
        for (int q = 0; q < 12; q++) gs = ffma2(g_pk[q], g_pk[q], gs);
        float lo, hi;
        upk2(gs, lo, hi);
        out[walker] = -0.5f * (lap + (lo + hi));
    }
}

extern "C" void kernel_launch(void* const* d_in, const int* in_sizes, int n_in,
                              void* d_out, int out_size)
{
    // metadata order: x [4096*8*3], W1 [24*256], b1 [256], W2 [256], b2 [1]
    const float* x  = (const float*)d_in[0];
    const float* W1 = (const float*)d_in[1];
    const float* b1 = (const float*)d_in[2];
    const float* W2 = (const float*)d_in[3];
    float* out = (float*)d_out;

    // Single graph node: 512 blocks x 128 threads; 8 walkers per block.
    kin_kernel<<<NWALK / 8, BLOCK>>>(x, W1, b1, W2, out);
}